// round 14
// baseline (speedup 1.0000x reference)
#include <cuda_runtime.h>

#define BB 4
#define TT 1024
#define DM 256
#define DS 64
#define MC 64
#define CS 68   // padded centroid row stride (floats)

__device__ float g_qkv[BB * TT * 384];
__device__ float g_z[BB * TT * DM];
__device__ float g_rinv[BB * TT];

typedef unsigned long long u64t;

__device__ __forceinline__ u64t pk2(float x, float y) {
    return ((u64t)__float_as_uint(y) << 32) | (u64t)__float_as_uint(x);
}
__device__ __forceinline__ float lo2(u64t p) { return __uint_as_float((unsigned)p); }
__device__ __forceinline__ float hi2(u64t p) { return __uint_as_float((unsigned)(p >> 32)); }
__device__ __forceinline__ u64t ffma2(u64t a, u64t b, u64t c) {
    u64t d;
    asm("fma.rn.f32x2 %0, %1, %2, %3;" : "=l"(d) : "l"(a), "l"(b), "l"(c));
    return d;
}
__device__ __forceinline__ u64t fmul2(u64t a, u64t b) {
    u64t d;
    asm("mul.rn.f32x2 %0, %1, %2;" : "=l"(d) : "l"(a), "l"(b));
    return d;
}
__device__ __forceinline__ u64t fadd2(u64t a, u64t b) {
    u64t d;
    asm("add.rn.f32x2 %0, %1, %2;" : "=l"(d) : "l"(a), "l"(b));
    return d;
}
// order-preserving float<->s32 bijection (monotone under SIGNED compare)
__device__ __forceinline__ int f2ord(float f) {
    int b = __float_as_int(f);
    return (b >= 0) ? b : (int)(~(unsigned)b ^ 0x80000000u);
}
__device__ __forceinline__ float ord2f(int o) {
    int b = (o >= 0) ? o : (int)(~((unsigned)o ^ 0x80000000u));
    return __int_as_float(b);
}
__device__ __forceinline__ int redux_maxi(int v) {
    int r; asm("redux.sync.max.s32 %0, %1, 0xffffffff;" : "=r"(r) : "r"(v)); return r;
}
__device__ __forceinline__ int redux_mini(int v) {
    int r; asm("redux.sync.min.s32 %0, %1, 0xffffffff;" : "=r"(r) : "r"(v)); return r;
}
__device__ __forceinline__ int redux_addi(int v) {
    int r; asm("redux.sync.add.s32 %0, %1, 0xffffffff;" : "=r"(r) : "r"(v)); return r;
}

// ---------------------------------------------------------------------------
// Pass 1a: q = l2norm(x@Wq + bq), k = l2norm(x@Wk + bk)
// ---------------------------------------------------------------------------
__global__ __launch_bounds__(128) void qk_kernel(
    const float* __restrict__ x, const float* __restrict__ Wq, const float* __restrict__ bq,
    const float* __restrict__ Wk, const float* __restrict__ bk) {
    __shared__ __align__(16) float sxa[8][DM];
    __shared__ float sred[4][8];
    int row0 = blockIdx.x * 8;
    int tid = threadIdx.x;
    int wp = tid >> 5, lane = tid & 31;
    for (int i = tid; i < 8 * DM / 4; i += 128)
        ((float4*)sxa)[i] = ((const float4*)(x + (size_t)row0 * DM))[i];
    __syncthreads();
    int col = tid & 63;
    const float* W = (tid < 64) ? Wq : Wk;
    float bias = (tid < 64) ? __ldg(bq + col) : __ldg(bk + col);
    u64t acc2[8];
#pragma unroll
    for (int r = 0; r < 8; r++) acc2[r] = 0ull;
    for (int i = 0; i < DM; i += 4) {
        float w0 = __ldg(W + (i + 0) * DS + col);
        float w1 = __ldg(W + (i + 1) * DS + col);
        float w2 = __ldg(W + (i + 2) * DS + col);
        float w3 = __ldg(W + (i + 3) * DS + col);
        u64t w2a = pk2(w0, w1), w2b = pk2(w2, w3);
#pragma unroll
        for (int r = 0; r < 8; r++) {
            const u64t* xr = (const u64t*)&sxa[r][i];
            acc2[r] = ffma2(xr[0], w2a, acc2[r]);
            acc2[r] = ffma2(xr[1], w2b, acc2[r]);
        }
    }
    float acc[8];
#pragma unroll
    for (int r = 0; r < 8; r++) acc[r] = bias + lo2(acc2[r]) + hi2(acc2[r]);
#pragma unroll
    for (int r = 0; r < 8; r++) {
        float s = acc[r] * acc[r];
#pragma unroll
        for (int o = 16; o > 0; o >>= 1) s += __shfl_xor_sync(0xffffffffu, s, o);
        if (lane == 0) sred[wp][r] = s;
    }
    __syncthreads();
    int base = (tid < 64) ? 0 : 2;
#pragma unroll
    for (int r = 0; r < 8; r++) {
        float tot = sred[base][r] + sred[base + 1][r];
        float den = fmaxf(__fsqrt_rn(tot), 1e-12f);
        g_qkv[(size_t)(row0 + r) * 384 + tid] = __fdiv_rn(acc[r], den);
    }
}

// ---------------------------------------------------------------------------
// Generic 256x256 GEMM (32 rows/block) with optional per-row input scaling.
// ---------------------------------------------------------------------------
__global__ __launch_bounds__(256) void gemm256(
    const float* __restrict__ in, int in_stride,
    const float* __restrict__ W, const float* __restrict__ b,
    float* __restrict__ out, int out_stride,
    const float* __restrict__ rowScale) {
    __shared__ __align__(16) float sxa[32][DM];
    int row0 = blockIdx.x * 32;
    int tid = threadIdx.x;
    if (rowScale) {
#pragma unroll
        for (int r = 0; r < 32; r++)
            sxa[r][tid] = in[(size_t)(row0 + r) * in_stride + tid] * __ldg(rowScale + row0 + r);
    } else {
#pragma unroll
        for (int r = 0; r < 32; r++)
            sxa[r][tid] = in[(size_t)(row0 + r) * in_stride + tid];
    }
    __syncthreads();
    float bias = __ldg(b + tid);
    u64t acc2[32];
#pragma unroll
    for (int r = 0; r < 32; r++) acc2[r] = 0ull;
    for (int i = 0; i < DM; i += 4) {
        float w0 = __ldg(W + (size_t)(i + 0) * DM + tid);
        float w1 = __ldg(W + (size_t)(i + 1) * DM + tid);
        float w2 = __ldg(W + (size_t)(i + 2) * DM + tid);
        float w3 = __ldg(W + (size_t)(i + 3) * DM + tid);
        u64t w2a = pk2(w0, w1), w2b = pk2(w2, w3);
#pragma unroll
        for (int r = 0; r < 32; r++) {
            const u64t* xr = (const u64t*)&sxa[r][i];
            acc2[r] = ffma2(xr[0], w2a, acc2[r]);
            acc2[r] = ffma2(xr[1], w2b, acc2[r]);
        }
    }
#pragma unroll
    for (int r = 0; r < 32; r++)
        out[(size_t)(row0 + r) * out_stride + tid] = bias + lo2(acc2[r]) + hi2(acc2[r]);
}

// ---------------------------------------------------------------------------
// Pass 2: sequential concept scan. One block per sequence. 256 threads.
// PIPELINED sims: sims for step t+1 computed post-B3 of step t against the
// already-committed state (only one centroid row changes; that row is fixed
// up by the committing warp). 2 barriers/step; no Phase-1 on critical path.
// ---------------------------------------------------------------------------
__global__ __launch_bounds__(256, 1) void scan_kernel(const float* __restrict__ g_ls) {
    __shared__ __align__(16) float s_cent[MC * CS];
    __shared__ __align__(16) u64t s_part64[8 * 128];   // [warp][p*32+lane] pair=(c, c+32)
    __shared__ __align__(16) float s_qkv[2][384];
    __shared__ float s_sims[2][MC];                    // ping-pong sims
    __shared__ float s_counts[MC];
    __shared__ int s_n, s_flags;

    const int b = blockIdx.x;
    const int tid = threadIdx.x;
    const int wp = tid >> 5;
    const int lane = tid & 31;
    const float* gq = g_qkv + (size_t)b * TT * 384;
    float* gz = g_z + (size_t)b * TT * DM;
    float* grv = g_rinv + (size_t)b * TT;
    const u64t NEG1 = pk2(-1.0f, -1.0f);

    for (int i = tid; i < MC * CS; i += 256) s_cent[i] = 0.0f;
    if (tid < MC) { s_counts[tid] = 0.0f; s_sims[0][tid] = 0.0f; s_sims[1][tid] = 0.0f; }
    if (tid == 0) s_n = 0;
    if (tid < 96) ((float4*)s_qkv[0])[tid] = __ldg(((const float4*)gq) + tid);
    u64t Vr[8][4];
#pragma unroll
    for (int i = 0; i < 8; i++)
#pragma unroll
        for (int j = 0; j < 4; j++) Vr[i][j] = 0ull;
    const float scale = fminf(expf(__ldg(g_ls)), 100.0f);
    __syncthreads();

    for (int t = 0; t < TT; t++) {
        const int buf = t & 1;
        const int nbuf = buf ^ 1;
        const float* qv = s_qkv[buf];
        const float* kv = qv + 64;
        const float* vv = qv + 128;
        const float* nxt = s_qkv[nbuf];

        const int n = s_n;
        const bool has = (n > 0);
        const int slot = (n < MC - 1) ? n : (MC - 1);

        // prefetch next step's q|k|v (published pre-B3)
        float4 pref;
        const bool doPref = (tid < 96) && (t + 1 < TT);
        if (doPref) pref = __ldg(((const float4*)(gq + (size_t)(t + 1) * 384)) + tid);

        // v_t slice, stride-32 columns: pairs (lane+64p, lane+64p+32)
        u64t vt2[4];
#pragma unroll
        for (int p = 0; p < 4; p++)
            vt2[p] = pk2(vv[lane + 64 * p], vv[lane + 64 * p + 32]);

        // --- chain A: masked argmax via s32 HW redux (sims already materialized) ---
        float sc0 = (lane < n) ? s_sims[buf][lane] : -1e9f;
        float sc1 = (lane + 32 < n) ? s_sims[buf][lane + 32] : -1e9f;
        int o0 = f2ord(sc0), o1 = f2ord(sc1);
        int omax = redux_maxi(max(o0, o1));
        int cand = (o0 == omax) ? lane : ((o1 == omax) ? (lane + 32) : (1 << 20));
        const int sel = redux_mini(cand);
        const float maxv = ord2f(omax);
        const int ownw = sel >> 3;

        // --- chain B: exps, weights, z partials (independent of redux) ---
        float e0 = __expf(sc0 * scale);
        float e1 = __expf(sc1 * scale);
        float esel = (wp < 4) ? e0 : e1;
        float wrow[8];
#pragma unroll
        for (int i = 0; i < 8; i++)
            wrow[i] = __shfl_sync(0xffffffffu, esel, ((wp & 3) << 3) + i);

        u64t acc2[4] = {0ull, 0ull, 0ull, 0ull};
#pragma unroll
        for (int i = 0; i < 8; i++) {
            u64t w2 = pk2(wrow[i], wrow[i]);
#pragma unroll
            for (int j = 0; j < 4; j++) acc2[j] = ffma2(w2, Vr[i][j], acc2[j]);
        }
        {
            u64t* pp = s_part64 + wp * 128 + lane;
            pp[0] = acc2[0]; pp[32] = acc2[1]; pp[64] = acc2[2]; pp[96] = acc2[3];
        }

        // region 1 (wp==ownw): residual via fixed-point redux + flags + coeffs
        float aco = 0.f, bco = 0.f;
        if (wp == ownw) {
            int r = sel & 7;
            u64t r0 = Vr[0][0], r1 = Vr[0][1], r2 = Vr[0][2], r3 = Vr[0][3];
#pragma unroll
            for (int i = 1; i < 8; i++)
                if (r == i) { r0 = Vr[i][0]; r1 = Vr[i][1]; r2 = Vr[i][2]; r3 = Vr[i][3]; }
            u64t racc = 0ull;
            u64t d0 = ffma2(vt2[0], NEG1, r0); racc = ffma2(d0, d0, racc);
            u64t d1 = ffma2(vt2[1], NEG1, r1); racc = ffma2(d1, d1, racc);
            u64t d2 = ffma2(vt2[2], NEG1, r2); racc = ffma2(d2, d2, racc);
            u64t d3 = ffma2(vt2[3], NEG1, r3); racc = ffma2(d3, d3, racc);
            float rsp = lo2(racc) + hi2(racc);
            int qs = redux_addi(__float2int_rn(rsp * 16384.0f));
            float cold = s_counts[sel];
            bco = __fdiv_rn(1.0f, cold + 1.0f);
            aco = cold * bco;
            if (lane == 0) {
                float rs = (float)qs * (1.0f / 16384.0f);
                float resid = __fsqrt_rn(rs * (1.0f / 256.0f));
                bool nlt = (n < MC);
                bool refine = has && nlt && ((maxv < 0.75f) || (resid > 1.0f));
                int da = (int)(((!has) || refine) && nlt);
                int du = (int)(has && !refine);
                s_flags = da | (du << 1);
            }
        }

        // region 2 (wp==ownw^1): speculative EMA + count snapshot
        const int ewp = ownw ^ 1;
        float ema0 = 0.f, ema1 = 0.f, cold2 = 0.f;
        if (wp == ewp) {
            float k0 = kv[lane], k1 = kv[lane + 32];
            float c0 = s_cent[sel * CS + lane];
            float c1 = s_cent[sel * CS + 32 + lane];
            float t0 = 0.9f * c0 + 0.1f * k0;
            float t1 = 0.9f * c1 + 0.1f * k1;
            int qsq = redux_addi(__float2int_rn((t0 * t0 + t1 * t1) * 268435456.0f));
            float ssq = (float)qsq * (1.0f / 268435456.0f);
            float den = fmaxf(__fsqrt_rn(ssq), 1e-12f);
            float inv = __fdiv_rn(1.0f, den);
            ema0 = t0 * inv;
            ema1 = t1 * inv;
            cold2 = s_counts[sel];
        }

        // region 3 (wp==ownw^2): esum via fixed-point redux + rinv store
        if (wp == (ownw ^ 2)) {
            int qe = redux_addi(__float2int_rn((e0 + e1) * 8388608.0f));
            if (lane == 0) {
                float esum = (float)qe * (1.0f / 8388608.0f);
                grv[t] = has ? __fdiv_rn(1.0f, esum) : 0.0f;
            }
        }

        // publish prefetched inputs into nxt buffer
        if (doPref) ((float4*)s_qkv[nbuf])[tid] = pref;
        __syncthreads();  // B3

        const int fl = s_flags;
        const int du = (fl >> 1) & 1;      // da == 1 - du
        const int crow = du ? sel : slot;

        // Phase 4a: unnormalized z reduce (128 threads, f32x2, conflict-free)
        if (tid < 128) {
            int l = tid & 31, p = tid >> 5;
            const u64t* zb = s_part64 + p * 32 + l;
            u64t s = zb[0];
#pragma unroll
            for (int w2 = 1; w2 < 8; w2++) s = fadd2(s, zb[w2 * 128]);
            int c0 = l + 64 * p;
            gz[(size_t)t * DM + c0] = lo2(s);
            gz[(size_t)t * DM + c0 + 32] = hi2(s);
        }
        // region 4: V commit (update row sel if du, else create row slot)
        if (wp == (crow >> 3)) {
            int r = crow & 7;
            float A = du ? aco : 0.0f;
            float B = du ? bco : 1.0f;
            u64t a2 = pk2(A, A), b2 = pk2(B, B);
#pragma unroll
            for (int i = 0; i < 8; i++)
                if (i == r) {
#pragma unroll
                    for (int j = 0; j < 4; j++)
                        Vr[i][j] = ffma2(Vr[i][j], a2, fmul2(vt2[j], b2));
                }
        }
        // speculative sims for step t+1 on pre-commit centroids (all threads);
        // row crow is fixed up by region 5 below.
        if (t + 1 < TT) {
            int m = tid >> 2, g = tid & 3;
            const u64t* cr = (const u64t*)(s_cent + m * CS + g * 16);
            const u64t* qr = (const u64t*)(nxt + g * 16);
            u64t c1 = fmul2(cr[0], qr[0]);
            u64t c2 = fmul2(cr[1], qr[1]);
            c1 = ffma2(cr[2], qr[2], c1);
            c2 = ffma2(cr[3], qr[3], c2);
            c1 = ffma2(cr[4], qr[4], c1);
            c2 = ffma2(cr[5], qr[5], c2);
            c1 = ffma2(cr[6], qr[6], c1);
            c2 = ffma2(cr[7], qr[7], c2);
            float a = (lo2(c1) + hi2(c1)) + (lo2(c2) + hi2(c2));
            a += __shfl_down_sync(0xffffffffu, a, 2, 4);
            a += __shfl_down_sync(0xffffffffu, a, 1, 4);
            if (g == 0 && m != crow) s_sims[nbuf][m] = a;
        }
        // region 5 (wp==ownw^1): centroid + counts + n commit + sim fix-up
        if (wp == ewp) {
            float v0 = du ? ema0 : kv[lane];
            float v1 = du ? ema1 : kv[lane + 32];
            s_cent[crow * CS + lane] = v0;
            s_cent[crow * CS + 32 + lane] = v1;
            // fix-up: sims_{t+1}[crow] = newcent . q_{t+1}  (|dot| <= 1)
            float qn0 = nxt[lane], qn1 = nxt[lane + 32];
            int qd = redux_addi(__float2int_rn((v0 * qn0 + v1 * qn1) * 16777216.0f));
            if (lane == 0) {
                s_sims[nbuf][crow] = (float)qd * (1.0f / 16777216.0f);
                s_counts[crow] = du ? (cold2 + 1.0f) : 1.0f;
                s_n = n + 1 - du;
            }
        }
        __syncthreads();  // B4
    }
}

extern "C" void kernel_launch(void* const* d_in, const int* in_sizes, int n_in,
                              void* d_out, int out_size) {
    const float* x  = (const float*)d_in[0];
    const float* Wq = (const float*)d_in[1];
    const float* bq = (const float*)d_in[2];
    const float* Wk = (const float*)d_in[3];
    const float* bk = (const float*)d_in[4];
    const float* Wv = (const float*)d_in[5];
    const float* bv = (const float*)d_in[6];
    const float* Wo = (const float*)d_in[7];
    const float* bo = (const float*)d_in[8];
    const float* ls = (const float*)d_in[9];
    float* out = (float*)d_out;

    float* qkv;
    cudaGetSymbolAddress((void**)&qkv, g_qkv);
    float* zbuf;
    cudaGetSymbolAddress((void**)&zbuf, g_z);
    float* rinvp;
    cudaGetSymbolAddress((void**)&rinvp, g_rinv);

    qk_kernel<<<(BB * TT) / 8, 128>>>(x, Wq, bq, Wk, bk);
    gemm256<<<(BB * TT) / 32, 256>>>(x, DM, Wv, bv, qkv + 128, 384, nullptr);
    scan_kernel<<<BB, 256>>>(ls);
    gemm256<<<(BB * TT) / 32, 256>>>(zbuf, DM, Wo, bo, out, DM, rinvp);
}